// round 12
// baseline (speedup 1.0000x reference)
#include <cuda_runtime.h>
#include <cuda_fp16.h>
#include <cstdint>

// Problem constants
#define NRES 384
#define CZ   128
#define NH   4
#define CH   32
#define HC   128              // NH*CH
#define RTOT (NRES*NRES)      // 147456
#define LN_EPS 1e-5f
#define Q_SCALE 0.17677669529663687f       // 1/sqrt(32)
#define LOG2E   1.4426950408889634f
#define QS_L2E  (Q_SCALE * LOG2E)

// Scratch (device globals). q/k/v/o/gate stored as packed fp16 pairs:
// 64 words = 128 halves per row; head h occupies words h*16..h*16+15.
__device__ uint32_t g_qw[RTOT * 64];
__device__ uint32_t g_kw[RTOT * 64];
__device__ uint32_t g_vw[RTOT * 64];
__device__ uint32_t g_ow[RTOT * 64];    // gated attention output, fp16 pairs
__device__ uint32_t g_gw[RTOT * 64];    // sigmoid gate, fp16 pairs
__device__ __half   g_trih[NH * RTOT];  // tri bias * log2e, fp16, [h][q*NRES+k]

// ---------------------------------------------------------------------------
// helpers
// ---------------------------------------------------------------------------
__device__ __forceinline__ void mma_f16(float c[4], const uint32_t a[4], const uint32_t b[2]) {
    asm volatile("mma.sync.aligned.m16n8k16.row.col.f32.f16.f16.f32 "
                 "{%0,%1,%2,%3}, {%4,%5,%6,%7}, {%8,%9}, {%0,%1,%2,%3};"
                 : "+f"(c[0]), "+f"(c[1]), "+f"(c[2]), "+f"(c[3])
                 : "r"(a[0]), "r"(a[1]), "r"(a[2]), "r"(a[3]),
                   "r"(b[0]), "r"(b[1]));
}
__device__ __forceinline__ uint32_t pack_h2(float a, float b) {
    __half2 h = __floats2half2_rn(a, b);
    return *reinterpret_cast<uint32_t*>(&h);
}
__device__ __forceinline__ float ex2(float x) {
    float r; asm("ex2.approx.f32 %0, %1;" : "=f"(r) : "f"(x)); return r;
}
__device__ __forceinline__ void ldsm_x2_t(uint32_t& r0, uint32_t& r1, uint32_t addr) {
    asm volatile("ldmatrix.sync.aligned.m8n8.x2.trans.shared.b16 {%0,%1}, [%2];"
                 : "=r"(r0), "=r"(r1) : "r"(addr));
}

// ---------------------------------------------------------------------------
// 1. Projection GEMM (fp16 mma), fused LayerNorm, tri via mma,
//    weight staging software-pipelined through registers.
// ---------------------------------------------------------------------------
#define AS2_STRIDE 68
#define BS2_STRIDE 136
#define PROJ_SMEM ((128*AS2_STRIDE + 64*BS2_STRIDE) * 4)

__global__ __launch_bounds__(256, 2) void proj_kernel(const float* __restrict__ z,
                                                      const float* __restrict__ gamma,
                                                      const float* __restrict__ beta,
                                                      const float* __restrict__ wb,
                                                      const float* __restrict__ wq,
                                                      const float* __restrict__ wk,
                                                      const float* __restrict__ wv,
                                                      const float* __restrict__ wg,
                                                      const float* __restrict__ bg) {
    extern __shared__ uint32_t psm[];
    uint32_t* As = psm;                    // [128][68] fp16 pairs (zn)
    uint32_t* Bs = psm + 128 * AS2_STRIDE; // [64][136] fp16 k-pairs

    const int r0   = blockIdx.x * 128;
    const int tid  = threadIdx.x;
    const int lane = tid & 31, warp = tid >> 5;
    const int g    = lane >> 2, tig = lane & 3;
    const int m_off = (warp >> 1) * 32;
    const int n_off = (warp & 1) * 64;

    // Per-thread weight-stage coordinates (8 chunks of 2 rows x 4 cols)
    const int wkp = tid >> 5;              // base k-pair row 0..7 (+8 per chunk)
    const int wn4 = (tid & 31) * 4;

    // --- A staging with fused LN (warp w handles row p*8+w) ---
    float4 gm = reinterpret_cast<const float4*>(gamma)[lane];
    float4 bt = reinterpret_cast<const float4*>(beta)[lane];
    #pragma unroll
    for (int p = 0; p < 16; p++) {
        int row = p * 8 + warp;            // local row 0..127
        float4 x = *reinterpret_cast<const float4*>(
            z + (size_t)(r0 + row) * CZ + lane * 4);
        float s  = x.x + x.y + x.z + x.w;
        float ss = x.x*x.x + x.y*x.y + x.z*x.z + x.w*x.w;
        #pragma unroll
        for (int o = 16; o; o >>= 1) {
            s  += __shfl_xor_sync(0xffffffffu, s,  o);
            ss += __shfl_xor_sync(0xffffffffu, ss, o);
        }
        float mean = s * (1.0f / CZ);
        float var  = ss * (1.0f / CZ) - mean * mean;
        float rstd = rsqrtf(var + LN_EPS);
        float n0 = (x.x - mean) * rstd * gm.x + bt.x;
        float n1 = (x.y - mean) * rstd * gm.y + bt.y;
        float n2 = (x.z - mean) * rstd * gm.z + bt.z;
        float n3 = (x.w - mean) * rstd * gm.w + bt.w;
        uint32_t* d = &As[row * AS2_STRIDE + lane * 2];
        d[0] = pack_h2(n0, n1);
        d[1] = pack_h2(n2, n3);
    }
    __syncthreads();

    // --- tri bias via mma: As @ wb (padded to 8 cols), scaled by log2e ---
    for (int idx = tid; idx < 64 * 8; idx += 256) {
        int kp = idx >> 3, n = idx & 7;
        float a = (n < NH) ? wb[(2 * kp    ) * NH + n] : 0.f;
        float b = (n < NH) ? wb[(2 * kp + 1) * NH + n] : 0.f;
        Bs[kp * BS2_STRIDE + n] = pack_h2(a, b);
    }
    __syncthreads();
    {
        float tacc[2][4] = {{0.f,0.f,0.f,0.f},{0.f,0.f,0.f,0.f}};
        #pragma unroll
        for (int ks = 0; ks < 8; ks++) {
            int kp8 = ks * 8;
            uint32_t bf[2];
            bf[0] = Bs[(kp8 + tig    ) * BS2_STRIDE + g];
            bf[1] = Bs[(kp8 + tig + 4) * BS2_STRIDE + g];
            #pragma unroll
            for (int mt = 0; mt < 2; mt++) {
                int row0 = m_off + mt * 16 + g;
                uint32_t af[4];
                af[0] = As[ row0      * AS2_STRIDE + kp8 + tig];
                af[1] = As[(row0 + 8) * AS2_STRIDE + kp8 + tig];
                af[2] = As[ row0      * AS2_STRIDE + kp8 + tig + 4];
                af[3] = As[(row0 + 8) * AS2_STRIDE + kp8 + tig + 4];
                mma_f16(tacc[mt], af, bf);
            }
        }
        if ((warp & 1) == 0 && tig < 2) {
            int h0 = 2 * tig, h1 = 2 * tig + 1;
            #pragma unroll
            for (int mt = 0; mt < 2; mt++) {
                int rg = r0 + m_off + mt * 16 + g;
                g_trih[(size_t)h0 * RTOT + rg    ] = __float2half(tacc[mt][0] * LOG2E);
                g_trih[(size_t)h1 * RTOT + rg    ] = __float2half(tacc[mt][1] * LOG2E);
                g_trih[(size_t)h0 * RTOT + rg + 8] = __float2half(tacc[mt][2] * LOG2E);
                g_trih[(size_t)h1 * RTOT + rg + 8] = __float2half(tacc[mt][3] * LOG2E);
            }
        }
    }

    // --- prefetch slab 0 weights into registers (packed fp16 pairs) ---
    uint32_t wpre[8][4];
    #pragma unroll
    for (int p = 0; p < 8; p++) {
        int kp = wkp + p * 8;
        float4 ra = *reinterpret_cast<const float4*>(wq + (size_t)(2 * kp    ) * HC + wn4);
        float4 rb = *reinterpret_cast<const float4*>(wq + (size_t)(2 * kp + 1) * HC + wn4);
        wpre[p][0] = pack_h2(ra.x, rb.x);
        wpre[p][1] = pack_h2(ra.y, rb.y);
        wpre[p][2] = pack_h2(ra.z, rb.z);
        wpre[p][3] = pack_h2(ra.w, rb.w);
    }

    for (int slab = 0; slab < 4; slab++) {
        __syncthreads();   // prior slab's mma reads of Bs done
        #pragma unroll
        for (int p = 0; p < 8; p++) {
            int kp = wkp + p * 8;
            uint32_t* d = &Bs[kp * BS2_STRIDE + wn4];
            d[0] = wpre[p][0]; d[1] = wpre[p][1]; d[2] = wpre[p][2]; d[3] = wpre[p][3];
        }
        __syncthreads();

        // prefetch next slab during the mma block
        if (slab < 3) {
            const float* Wn = (slab == 0) ? wk : (slab == 1) ? wv : wg;
            #pragma unroll
            for (int p = 0; p < 8; p++) {
                int kp = wkp + p * 8;
                float4 ra = *reinterpret_cast<const float4*>(Wn + (size_t)(2 * kp    ) * HC + wn4);
                float4 rb = *reinterpret_cast<const float4*>(Wn + (size_t)(2 * kp + 1) * HC + wn4);
                wpre[p][0] = pack_h2(ra.x, rb.x);
                wpre[p][1] = pack_h2(ra.y, rb.y);
                wpre[p][2] = pack_h2(ra.z, rb.z);
                wpre[p][3] = pack_h2(ra.w, rb.w);
            }
        }

        float acc[2][8][4];
        #pragma unroll
        for (int mt = 0; mt < 2; mt++)
            #pragma unroll
            for (int nt = 0; nt < 8; nt++)
                #pragma unroll
                for (int e = 0; e < 4; e++) acc[mt][nt][e] = 0.f;

        #pragma unroll
        for (int ks = 0; ks < 8; ks++) {
            int kp8 = ks * 8;
            uint32_t af[2][4];
            #pragma unroll
            for (int mt = 0; mt < 2; mt++) {
                int row0 = m_off + mt * 16 + g;
                af[mt][0] = As[ row0      * AS2_STRIDE + kp8 + tig];
                af[mt][1] = As[(row0 + 8) * AS2_STRIDE + kp8 + tig];
                af[mt][2] = As[ row0      * AS2_STRIDE + kp8 + tig + 4];
                af[mt][3] = As[(row0 + 8) * AS2_STRIDE + kp8 + tig + 4];
            }
            uint32_t bf[8][2];
            #pragma unroll
            for (int nt = 0; nt < 8; nt++) {
                int col = n_off + nt * 8 + g;
                bf[nt][0] = Bs[(kp8 + tig    ) * BS2_STRIDE + col];
                bf[nt][1] = Bs[(kp8 + tig + 4) * BS2_STRIDE + col];
            }
            #pragma unroll
            for (int mt = 0; mt < 2; mt++)
                #pragma unroll
                for (int nt = 0; nt < 8; nt++)
                    mma_f16(acc[mt][nt], af[mt], bf[nt]);
        }

        #pragma unroll
        for (int mt = 0; mt < 2; mt++) {
            int rowa = r0 + m_off + mt * 16 + g;
            #pragma unroll
            for (int nt = 0; nt < 8; nt++) {
                int col = n_off + nt * 8 + tig * 2;      // even
                float c0 = acc[mt][nt][0], c1 = acc[mt][nt][1];
                float c2 = acc[mt][nt][2], c3 = acc[mt][nt][3];
                size_t w0 = (size_t)rowa * 64 + (col >> 1);
                size_t w1 = (size_t)(rowa + 8) * 64 + (col >> 1);
                if (slab == 0) {
                    g_qw[w0] = pack_h2(c0 * QS_L2E, c1 * QS_L2E);
                    g_qw[w1] = pack_h2(c2 * QS_L2E, c3 * QS_L2E);
                } else if (slab == 1) {
                    g_kw[w0] = pack_h2(c0, c1);
                    g_kw[w1] = pack_h2(c2, c3);
                } else if (slab == 2) {
                    g_vw[w0] = pack_h2(c0, c1);
                    g_vw[w1] = pack_h2(c2, c3);
                } else {
                    float b0 = bg[col], b1 = bg[col + 1];
                    g_gw[w0] = pack_h2(1.f / (1.f + __expf(-(c0 + b0))),
                                       1.f / (1.f + __expf(-(c1 + b1))));
                    g_gw[w1] = pack_h2(1.f / (1.f + __expf(-(c2 + b0))),
                                       1.f / (1.f + __expf(-(c3 + b1))));
                }
            }
        }
    }
}

// ---------------------------------------------------------------------------
// 2. Attention (fp16 mma, fp32 accum): one block per (i,h), 384 thr / 12 warps,
//    32 queries per warp. exp2-domain softmax; tri/mask prefetched per iter.
// ---------------------------------------------------------------------------
#define KV_STRIDE 20
#define SMEM_ATTN ((NRES*KV_STRIDE*2 + NRES) * 4)

__global__ __launch_bounds__(384, 1) void attn_kernel(const float* __restrict__ mask) {
    extern __shared__ uint32_t smu[];
    uint32_t* Kh = smu;                        // [384][20] fp16 pairs
    uint32_t* Vh = smu + NRES * KV_STRIDE;     // [384][20] fp16 pairs
    float*    mb = (float*)(smu + 2 * NRES * KV_STRIDE);  // [384]

    const int i = blockIdx.x, h = blockIdx.y;
    const int tid = threadIdx.x;
    const int lane = tid & 31, warp = tid >> 5;
    const int g = lane >> 2, tig = lane & 3;
    const int m_off = warp * 32;
    const size_t rowbase = (size_t)i * NRES;
    const int hw = h * 16;

    // --- stage Q through Kh, grab fragments ---
    #pragma unroll
    for (int p = 0; p < 4; p++) {
        int idx = tid + p * 384;
        int row = idx >> 2, c = (idx & 3) * 4;
        *reinterpret_cast<uint4*>(Kh + row * KV_STRIDE + c) =
            *reinterpret_cast<const uint4*>(g_qw + (rowbase + row) * 64 + hw + c);
    }
    __syncthreads();
    uint32_t qf[2][2][4];
    #pragma unroll
    for (int mt = 0; mt < 2; mt++) {
        int r = m_off + mt * 16 + g;
        #pragma unroll
        for (int kd = 0; kd < 2; kd++) {
            qf[mt][kd][0] = Kh[ r      * KV_STRIDE + kd * 8 + tig];
            qf[mt][kd][1] = Kh[(r + 8) * KV_STRIDE + kd * 8 + tig];
            qf[mt][kd][2] = Kh[ r      * KV_STRIDE + kd * 8 + tig + 4];
            qf[mt][kd][3] = Kh[(r + 8) * KV_STRIDE + kd * 8 + tig + 4];
        }
    }
    __syncthreads();

    // --- load K, V, mask ---
    #pragma unroll
    for (int p = 0; p < 4; p++) {
        int idx = tid + p * 384;
        int row = idx >> 2, c = (idx & 3) * 4;
        *reinterpret_cast<uint4*>(Kh + row * KV_STRIDE + c) =
            *reinterpret_cast<const uint4*>(g_kw + (rowbase + row) * 64 + hw + c);
        *reinterpret_cast<uint4*>(Vh + row * KV_STRIDE + c) =
            *reinterpret_cast<const uint4*>(g_vw + (rowbase + row) * 64 + hw + c);
    }
    mb[tid] = 1.4426950409e9f * (mask[rowbase + tid] - 1.f);
    __syncthreads();

    float oacc[2][4][4];
    #pragma unroll
    for (int mt = 0; mt < 2; mt++)
        #pragma unroll
        for (int nt = 0; nt < 4; nt++)
            #pragma unroll
            for (int e = 0; e < 4; e++) oacc[mt][nt][e] = 0.f;
    float lsum[2][2] = {{0.f, 0.f}, {0.f, 0.f}};

    const __half* tribh = g_trih + (size_t)h * RTOT;
    const uint32_t vbase = (uint32_t)__cvta_generic_to_shared(Vh) + (lane & 15) * (KV_STRIDE * 4);

    for (int kb = 0; kb < NRES; kb += 32) {
        // prefetch tri (fp16 words) and mask for this iteration up front
        uint32_t trw[2][2][4];     // [mt][row g/g+8][nt]
        float2   mbp[4];
        #pragma unroll
        for (int nt = 0; nt < 4; nt++) {
            int k0 = kb + nt * 8 + 2 * tig;
            mbp[nt] = *reinterpret_cast<float2*>(&mb[k0]);
            #pragma unroll
            for (int mt = 0; mt < 2; mt++) {
                int r = m_off + mt * 16 + g;
                trw[mt][0][nt] = *reinterpret_cast<const uint32_t*>(&tribh[(size_t)r * NRES + k0]);
                trw[mt][1][nt] = *reinterpret_cast<const uint32_t*>(&tribh[(size_t)(r + 8) * NRES + k0]);
            }
        }

        uint32_t pk[2][4][2];
        #pragma unroll
        for (int mt = 0; mt < 2; mt++) {
            float s[4][4];
            #pragma unroll
            for (int nt = 0; nt < 4; nt++)
                #pragma unroll
                for (int e = 0; e < 4; e++) s[nt][e] = 0.f;
            #pragma unroll
            for (int kd = 0; kd < 2; kd++)
                #pragma unroll
                for (int nt = 0; nt < 4; nt++) {
                    int krow = kb + nt * 8 + g;
                    uint32_t b[2] = {Kh[krow * KV_STRIDE + kd * 8 + tig],
                                     Kh[krow * KV_STRIDE + kd * 8 + tig + 4]};
                    mma_f16(s[nt], qf[mt][kd], b);
                }
            #pragma unroll
            for (int nt = 0; nt < 4; nt++) {
                float2 b0 = __half22float2(*reinterpret_cast<__half2*>(&trw[mt][0][nt]));
                float2 b1 = __half22float2(*reinterpret_cast<__half2*>(&trw[mt][1][nt]));
                float p00 = ex2(s[nt][0] + b0.x + mbp[nt].x);
                float p01 = ex2(s[nt][1] + b0.y + mbp[nt].y);
                float p10 = ex2(s[nt][2] + b1.x + mbp[nt].x);
                float p11 = ex2(s[nt][3] + b1.y + mbp[nt].y);
                lsum[mt][0] += p00 + p01;
                lsum[mt][1] += p10 + p11;
                pk[mt][nt][0] = pack_h2(p00, p01);   // row g
                pk[mt][nt][1] = pack_h2(p10, p11);   // row g+8
            }
        }

        // O += P V : B-frag via ldmatrix.trans of V rows (keys-major)
        #pragma unroll
        for (int kg = 0; kg < 2; kg++) {
            #pragma unroll
            for (int nt = 0; nt < 4; nt++) {
                uint32_t b0, b1;
                ldsm_x2_t(b0, b1, vbase + (kb + kg * 16) * (KV_STRIDE * 4) + nt * 16);
                uint32_t bq[2] = {b0, b1};
                uint32_t a0[4] = {pk[0][2*kg][0], pk[0][2*kg][1], pk[0][2*kg+1][0], pk[0][2*kg+1][1]};
                mma_f16(oacc[0][nt], a0, bq);
                uint32_t a1[4] = {pk[1][2*kg][0], pk[1][2*kg][1], pk[1][2*kg+1][0], pk[1][2*kg+1][1]};
                mma_f16(oacc[1][nt], a1, bq);
            }
        }
    }

    // epilogue: l reduce across quad, gate (fp16), write O as fp16 words
    #pragma unroll
    for (int mt = 0; mt < 2; mt++) {
        float la = lsum[mt][0], lb = lsum[mt][1];
        la += __shfl_xor_sync(0xffffffffu, la, 1);
        la += __shfl_xor_sync(0xffffffffu, la, 2);
        lb += __shfl_xor_sync(0xffffffffu, lb, 1);
        lb += __shfl_xor_sync(0xffffffffu, lb, 2);
        float ia = 1.f / la, ib = 1.f / lb;
        size_t rowa = rowbase + m_off + mt * 16 + g;
        size_t rowb = rowa + 8;
        #pragma unroll
        for (int nt = 0; nt < 4; nt++) {
            uint32_t gaw = g_gw[rowa * 64 + hw + nt * 4 + tig];
            uint32_t gbw = g_gw[rowb * 64 + hw + nt * 4 + tig];
            float2 ga = __half22float2(*reinterpret_cast<__half2*>(&gaw));
            float2 gb = __half22float2(*reinterpret_cast<__half2*>(&gbw));
            g_ow[rowa * 64 + hw + nt * 4 + tig] =
                pack_h2(oacc[mt][nt][0] * ia * ga.x, oacc[mt][nt][1] * ia * ga.y);
            g_ow[rowb * 64 + hw + nt * 4 + tig] =
                pack_h2(oacc[mt][nt][2] * ib * gb.x, oacc[mt][nt][3] * ib * gb.y);
        }
    }
}

// ---------------------------------------------------------------------------
// 3. Output GEMM (fp16 mma): g_ow[147456,128h] @ w_o[128,128] + b_o -> out
// ---------------------------------------------------------------------------
#define OAS_STRIDE 68
#define OBS_STRIDE 136
#define OUT_SMEM ((128*OAS_STRIDE + 64*OBS_STRIDE) * 4)

__global__ __launch_bounds__(256, 2) void out_kernel(const float* __restrict__ wo,
                                                     const float* __restrict__ bo,
                                                     float* __restrict__ out) {
    extern __shared__ uint32_t osm[];
    uint32_t* As = osm;                    // [128][68]
    uint32_t* Bs = osm + 128 * OAS_STRIDE; // [64][136]

    const int r0 = blockIdx.x * 128;
    const int tid  = threadIdx.x;
    const int lane = tid & 31, warp = tid >> 5;
    const int g    = lane >> 2, tig = lane & 3;
    const int m_off = (warp >> 1) * 32;
    const int n_off = (warp & 1) * 64;

    // Stage A: copy fp16 words directly
    #pragma unroll
    for (int p = 0; p < 8; p++) {
        int idx = tid + p * 256;
        int row = idx >> 4, c4 = (idx & 15) * 4;
        *reinterpret_cast<uint4*>(As + row * OAS_STRIDE + c4) =
            *reinterpret_cast<const uint4*>(g_ow + (size_t)(r0 + row) * 64 + c4);
    }
    // Stage B (wo) as k-pairs
    #pragma unroll
    for (int p = 0; p < 8; p++) {
        int idx = tid + p * 256;
        int kp = idx >> 5, n4 = (idx & 31) * 4;
        float4 ra = *reinterpret_cast<const float4*>(wo + (size_t)(2 * kp    ) * CZ + n4);
        float4 rb = *reinterpret_cast<const float4*>(wo + (size_t)(2 * kp + 1) * CZ + n4);
        uint32_t* d = &Bs[kp * OBS_STRIDE + n4];
        d[0] = pack_h2(ra.x, rb.x);
        d[1] = pack_h2(ra.y, rb.y);
        d[2] = pack_h2(ra.z, rb.z);
        d[3] = pack_h2(ra.w, rb.w);
    }
    __syncthreads();

    float acc[2][8][4];
    #pragma unroll
    for (int mt = 0; mt < 2; mt++)
        #pragma unroll
        for (int nt = 0; nt < 8; nt++)
            #pragma unroll
            for (int e = 0; e < 4; e++) acc[mt][nt][e] = 0.f;

    #pragma unroll
    for (int ks = 0; ks < 8; ks++) {
        int kp8 = ks * 8;
        uint32_t af[2][4];
        #pragma unroll
        for (int mt = 0; mt < 2; mt++) {
            int row0 = m_off + mt * 16 + g;
            af[mt][0] = As[ row0      * OAS_STRIDE + kp8 + tig];
            af[mt][1] = As[(row0 + 8) * OAS_STRIDE + kp8 + tig];
            af[mt][2] = As[ row0      * OAS_STRIDE + kp8 + tig + 4];
            af[mt][3] = As[(row0 + 8) * OAS_STRIDE + kp8 + tig + 4];
        }
        uint32_t bf[8][2];
        #pragma unroll
        for (int nt = 0; nt < 8; nt++) {
            int col = n_off + nt * 8 + g;
            bf[nt][0] = Bs[(kp8 + tig    ) * OBS_STRIDE + col];
            bf[nt][1] = Bs[(kp8 + tig + 4) * OBS_STRIDE + col];
        }
        #pragma unroll
        for (int mt = 0; mt < 2; mt++)
            #pragma unroll
            for (int nt = 0; nt < 8; nt++)
                mma_f16(acc[mt][nt], af[mt], bf[nt]);
    }

    #pragma unroll
    for (int mt = 0; mt < 2; mt++) {
        #pragma unroll
        for (int nt = 0; nt < 8; nt++) {
            int row = r0 + m_off + mt * 16 + g;
            int col = n_off + nt * 8 + tig * 2;
            float b0 = bo[col], b1 = bo[col + 1];
            *reinterpret_cast<float2*>(out + (size_t)row * CZ + col) =
                make_float2(acc[mt][nt][0] + b0, acc[mt][nt][1] + b1);
            *reinterpret_cast<float2*>(out + (size_t)(row + 8) * CZ + col) =
                make_float2(acc[mt][nt][2] + b0, acc[mt][nt][3] + b1);
        }
    }
}

// ---------------------------------------------------------------------------
extern "C" void kernel_launch(void* const* d_in, const int* in_sizes, int n_in,
                              void* d_out, int out_size) {
    const float* z      = (const float*)d_in[0];
    const float* mask   = (const float*)d_in[1];
    const float* gamma  = (const float*)d_in[2];
    const float* beta   = (const float*)d_in[3];
    const float* w_bias = (const float*)d_in[4];
    const float* w_q    = (const float*)d_in[5];
    const float* w_k    = (const float*)d_in[6];
    const float* w_v    = (const float*)d_in[7];
    const float* w_g    = (const float*)d_in[8];
    const float* b_g    = (const float*)d_in[9];
    const float* w_o    = (const float*)d_in[10];
    const float* b_o    = (const float*)d_in[11];
    float* out = (float*)d_out;

    (void)cudaFuncSetAttribute(proj_kernel, cudaFuncAttributeMaxDynamicSharedMemorySize, PROJ_SMEM);
    (void)cudaFuncSetAttribute(attn_kernel, cudaFuncAttributeMaxDynamicSharedMemorySize, SMEM_ATTN);
    (void)cudaFuncSetAttribute(out_kernel,  cudaFuncAttributeMaxDynamicSharedMemorySize, OUT_SMEM);

    proj_kernel<<<RTOT / 128, 256, PROJ_SMEM>>>(z, gamma, beta, w_bias,
                                                w_q, w_k, w_v, w_g, b_g);
    attn_kernel<<<dim3(NRES, NH), 384, SMEM_ATTN>>>(mask);
    out_kernel<<<RTOT / 128, 256, OUT_SMEM>>>(w_o, b_o, out);
}

// round 14
// speedup vs baseline: 1.0752x; 1.0752x over previous
#include <cuda_runtime.h>
#include <cuda_fp16.h>
#include <cstdint>

// Problem constants
#define NRES 384
#define CZ   128
#define NH   4
#define CH   32
#define HC   128              // NH*CH
#define RTOT (NRES*NRES)      // 147456
#define LN_EPS 1e-5f
#define Q_SCALE 0.17677669529663687f       // 1/sqrt(32)
#define LOG2E   1.4426950408889634f
#define QS_L2E  (Q_SCALE * LOG2E)

// Scratch (device globals). q/k/v/o/gate stored as packed fp16 pairs:
// 64 words = 128 halves per row; head h occupies words h*16..h*16+15.
__device__ uint32_t g_qw[RTOT * 64];
__device__ uint32_t g_kw[RTOT * 64];
__device__ uint32_t g_vw[RTOT * 64];
__device__ uint32_t g_ow[RTOT * 64];    // gated attention output, fp16 pairs
__device__ uint32_t g_gw[RTOT * 64];    // sigmoid gate, fp16 pairs
__device__ __half   g_trih[NH * RTOT];  // tri bias * log2e, fp16, [h][q*NRES+k]
// Pre-converted weights, packed fp16 k-pairs: [w][kp*128 + n], w: 0q 1k 2v 3g 4o
__device__ uint32_t g_w16[5 * 64 * 128];

// ---------------------------------------------------------------------------
// helpers
// ---------------------------------------------------------------------------
__device__ __forceinline__ void mma_f16(float c[4], const uint32_t a[4], const uint32_t b[2]) {
    asm volatile("mma.sync.aligned.m16n8k16.row.col.f32.f16.f16.f32 "
                 "{%0,%1,%2,%3}, {%4,%5,%6,%7}, {%8,%9}, {%0,%1,%2,%3};"
                 : "+f"(c[0]), "+f"(c[1]), "+f"(c[2]), "+f"(c[3])
                 : "r"(a[0]), "r"(a[1]), "r"(a[2]), "r"(a[3]),
                   "r"(b[0]), "r"(b[1]));
}
__device__ __forceinline__ uint32_t pack_h2(float a, float b) {
    __half2 h = __floats2half2_rn(a, b);
    return *reinterpret_cast<uint32_t*>(&h);
}
__device__ __forceinline__ float ex2(float x) {
    float r; asm("ex2.approx.f32 %0, %1;" : "=f"(r) : "f"(x)); return r;
}
__device__ __forceinline__ void ldsm_x2_t(uint32_t& r0, uint32_t& r1, uint32_t addr) {
    asm volatile("ldmatrix.sync.aligned.m8n8.x2.trans.shared.b16 {%0,%1}, [%2];"
                 : "=r"(r0), "=r"(r1) : "r"(addr));
}
__device__ __forceinline__ void cp_async16(uint32_t saddr, const void* gptr) {
    asm volatile("cp.async.ca.shared.global [%0], [%1], 16;" :: "r"(saddr), "l"(gptr));
}
#define CP_COMMIT() asm volatile("cp.async.commit_group;" ::: "memory")
#define CP_WAIT0()  asm volatile("cp.async.wait_group 0;" ::: "memory")

// ---------------------------------------------------------------------------
// 0. Weight prep: fp32 [128][128] -> packed fp16 k-pair words [64][128]
// ---------------------------------------------------------------------------
__global__ __launch_bounds__(256) void prep_kernel(const float* __restrict__ wq,
                                                   const float* __restrict__ wk,
                                                   const float* __restrict__ wv,
                                                   const float* __restrict__ wg,
                                                   const float* __restrict__ wo) {
    int idx = blockIdx.x * 256 + threadIdx.x;      // 0 .. 40959
    int w = idx >> 13;                              // /8192
    int r = idx & 8191;
    int kp = r >> 7, n = r & 127;
    const float* W = (w == 0) ? wq : (w == 1) ? wk : (w == 2) ? wv : (w == 3) ? wg : wo;
    g_w16[idx] = pack_h2(W[(2 * kp) * 128 + n], W[(2 * kp + 1) * 128 + n]);
}

// ---------------------------------------------------------------------------
// 1. Projection GEMM (fp16 mma), fused LayerNorm, tri via mma.
//    Weight staging double-buffered in smem via cp.async (no register cost).
// ---------------------------------------------------------------------------
#define AS2_STRIDE 68
#define BS2_STRIDE 136
#define PROJ_SMEM ((128*AS2_STRIDE + 2*64*BS2_STRIDE) * 4)

__global__ __launch_bounds__(256, 2) void proj_kernel(const float* __restrict__ z,
                                                      const float* __restrict__ gamma,
                                                      const float* __restrict__ beta,
                                                      const float* __restrict__ wb,
                                                      const float* __restrict__ bg) {
    extern __shared__ uint32_t psm[];
    uint32_t* As  = psm;                       // [128][68] fp16 pairs (zn)
    uint32_t* Bs0 = psm + 128 * AS2_STRIDE;    // [64][136]
    uint32_t* Bs1 = Bs0 + 64 * BS2_STRIDE;     // [64][136]

    const int r0   = blockIdx.x * 128;
    const int tid  = threadIdx.x;
    const int lane = tid & 31, warp = tid >> 5;
    const int g    = lane >> 2, tig = lane & 3;
    const int m_off = (warp >> 1) * 32;
    const int n_off = (warp & 1) * 64;

    const uint32_t bs0a = (uint32_t)__cvta_generic_to_shared(Bs0);
    const uint32_t bs1a = (uint32_t)__cvta_generic_to_shared(Bs1);

    // --- A staging with fused LN (warp w handles row p*8+w) ---
    float4 gm = reinterpret_cast<const float4*>(gamma)[lane];
    float4 bt = reinterpret_cast<const float4*>(beta)[lane];
    #pragma unroll
    for (int p = 0; p < 16; p++) {
        int row = p * 8 + warp;            // local row 0..127
        float4 x = *reinterpret_cast<const float4*>(
            z + (size_t)(r0 + row) * CZ + lane * 4);
        float s  = x.x + x.y + x.z + x.w;
        float ss = x.x*x.x + x.y*x.y + x.z*x.z + x.w*x.w;
        #pragma unroll
        for (int o = 16; o; o >>= 1) {
            s  += __shfl_xor_sync(0xffffffffu, s,  o);
            ss += __shfl_xor_sync(0xffffffffu, ss, o);
        }
        float mean = s * (1.0f / CZ);
        float var  = ss * (1.0f / CZ) - mean * mean;
        float rstd = rsqrtf(var + LN_EPS);
        float n0 = (x.x - mean) * rstd * gm.x + bt.x;
        float n1 = (x.y - mean) * rstd * gm.y + bt.y;
        float n2 = (x.z - mean) * rstd * gm.z + bt.z;
        float n3 = (x.w - mean) * rstd * gm.w + bt.w;
        uint32_t* d = &As[row * AS2_STRIDE + lane * 2];
        d[0] = pack_h2(n0, n1);
        d[1] = pack_h2(n2, n3);
    }

    // Prefetch slab 0 weights into Bs1 via cp.async (overlaps tri phase)
    // 64 rows x 128 words = 2048 16B chunks -> 8 per thread
    #pragma unroll
    for (int p = 0; p < 8; p++) {
        int c = tid + p * 256;
        int kp = c >> 5, n4 = (c & 31) * 4;
        cp_async16(bs1a + (kp * BS2_STRIDE + n4) * 4, g_w16 + kp * 128 + n4);
    }
    CP_COMMIT();
    __syncthreads();   // As visible to all

    // --- tri bias via mma: As @ wb (padded to 8 cols), scaled by log2e ---
    for (int idx = tid; idx < 64 * 8; idx += 256) {
        int kp = idx >> 3, n = idx & 7;
        float a = (n < NH) ? wb[(2 * kp    ) * NH + n] : 0.f;
        float b = (n < NH) ? wb[(2 * kp + 1) * NH + n] : 0.f;
        Bs0[kp * BS2_STRIDE + n] = pack_h2(a, b);
    }
    __syncthreads();
    {
        float tacc[2][4] = {{0.f,0.f,0.f,0.f},{0.f,0.f,0.f,0.f}};
        #pragma unroll
        for (int ks = 0; ks < 8; ks++) {
            int kp8 = ks * 8;
            uint32_t bf[2];
            bf[0] = Bs0[(kp8 + tig    ) * BS2_STRIDE + g];
            bf[1] = Bs0[(kp8 + tig + 4) * BS2_STRIDE + g];
            #pragma unroll
            for (int mt = 0; mt < 2; mt++) {
                int row0 = m_off + mt * 16 + g;
                uint32_t af[4];
                af[0] = As[ row0      * AS2_STRIDE + kp8 + tig];
                af[1] = As[(row0 + 8) * AS2_STRIDE + kp8 + tig];
                af[2] = As[ row0      * AS2_STRIDE + kp8 + tig + 4];
                af[3] = As[(row0 + 8) * AS2_STRIDE + kp8 + tig + 4];
                mma_f16(tacc[mt], af, bf);
            }
        }
        if ((warp & 1) == 0 && tig < 2) {
            int h0 = 2 * tig, h1 = 2 * tig + 1;
            #pragma unroll
            for (int mt = 0; mt < 2; mt++) {
                int rg = r0 + m_off + mt * 16 + g;
                g_trih[(size_t)h0 * RTOT + rg    ] = __float2half(tacc[mt][0] * LOG2E);
                g_trih[(size_t)h1 * RTOT + rg    ] = __float2half(tacc[mt][1] * LOG2E);
                g_trih[(size_t)h0 * RTOT + rg + 8] = __float2half(tacc[mt][2] * LOG2E);
                g_trih[(size_t)h1 * RTOT + rg + 8] = __float2half(tacc[mt][3] * LOG2E);
            }
        }
    }

    for (int slab = 0; slab < 4; slab++) {
        uint32_t* Bsc = (slab & 1) ? Bs0 : Bs1;          // slab0->Bs1, slab1->Bs0, ...
        CP_WAIT0();
        __syncthreads();    // weights landed; all warps done with the other buffer

        if (slab < 3) {
            uint32_t dsta = (slab & 1) ? bs1a : bs0a;    // other buffer
            const uint32_t* src = g_w16 + (slab + 1) * 8192;
            #pragma unroll
            for (int p = 0; p < 8; p++) {
                int c = tid + p * 256;
                int kp = c >> 5, n4 = (c & 31) * 4;
                cp_async16(dsta + (kp * BS2_STRIDE + n4) * 4, src + kp * 128 + n4);
            }
            CP_COMMIT();
        }

        float acc[2][8][4];
        #pragma unroll
        for (int mt = 0; mt < 2; mt++)
            #pragma unroll
            for (int nt = 0; nt < 8; nt++)
                #pragma unroll
                for (int e = 0; e < 4; e++) acc[mt][nt][e] = 0.f;

        #pragma unroll
        for (int ks = 0; ks < 8; ks++) {
            int kp8 = ks * 8;
            uint32_t af[2][4];
            #pragma unroll
            for (int mt = 0; mt < 2; mt++) {
                int row0 = m_off + mt * 16 + g;
                af[mt][0] = As[ row0      * AS2_STRIDE + kp8 + tig];
                af[mt][1] = As[(row0 + 8) * AS2_STRIDE + kp8 + tig];
                af[mt][2] = As[ row0      * AS2_STRIDE + kp8 + tig + 4];
                af[mt][3] = As[(row0 + 8) * AS2_STRIDE + kp8 + tig + 4];
            }
            uint32_t bf[8][2];
            #pragma unroll
            for (int nt = 0; nt < 8; nt++) {
                int col = n_off + nt * 8 + g;
                bf[nt][0] = Bsc[(kp8 + tig    ) * BS2_STRIDE + col];
                bf[nt][1] = Bsc[(kp8 + tig + 4) * BS2_STRIDE + col];
            }
            #pragma unroll
            for (int mt = 0; mt < 2; mt++)
                #pragma unroll
                for (int nt = 0; nt < 8; nt++)
                    mma_f16(acc[mt][nt], af[mt], bf[nt]);
        }

        #pragma unroll
        for (int mt = 0; mt < 2; mt++) {
            int rowa = r0 + m_off + mt * 16 + g;
            #pragma unroll
            for (int nt = 0; nt < 8; nt++) {
                int col = n_off + nt * 8 + tig * 2;      // even
                float c0 = acc[mt][nt][0], c1 = acc[mt][nt][1];
                float c2 = acc[mt][nt][2], c3 = acc[mt][nt][3];
                size_t w0 = (size_t)rowa * 64 + (col >> 1);
                size_t w1 = (size_t)(rowa + 8) * 64 + (col >> 1);
                if (slab == 0) {
                    g_qw[w0] = pack_h2(c0 * QS_L2E, c1 * QS_L2E);
                    g_qw[w1] = pack_h2(c2 * QS_L2E, c3 * QS_L2E);
                } else if (slab == 1) {
                    g_kw[w0] = pack_h2(c0, c1);
                    g_kw[w1] = pack_h2(c2, c3);
                } else if (slab == 2) {
                    g_vw[w0] = pack_h2(c0, c1);
                    g_vw[w1] = pack_h2(c2, c3);
                } else {
                    float b0 = bg[col], b1 = bg[col + 1];
                    g_gw[w0] = pack_h2(1.f / (1.f + __expf(-(c0 + b0))),
                                       1.f / (1.f + __expf(-(c1 + b1))));
                    g_gw[w1] = pack_h2(1.f / (1.f + __expf(-(c2 + b0))),
                                       1.f / (1.f + __expf(-(c3 + b1))));
                }
            }
        }
    }
}

// ---------------------------------------------------------------------------
// 2. Attention (fp16 mma, fp32 accum): one block per (i,h), 384 thr / 12 warps,
//    32 queries per warp. exp2-domain softmax; tri/mask prefetched per iter.
// ---------------------------------------------------------------------------
#define KV_STRIDE 20
#define SMEM_ATTN ((NRES*KV_STRIDE*2 + NRES) * 4)

__global__ __launch_bounds__(384, 1) void attn_kernel(const float* __restrict__ mask) {
    extern __shared__ uint32_t smu[];
    uint32_t* Kh = smu;                        // [384][20] fp16 pairs
    uint32_t* Vh = smu + NRES * KV_STRIDE;     // [384][20] fp16 pairs
    float*    mb = (float*)(smu + 2 * NRES * KV_STRIDE);  // [384]

    const int i = blockIdx.x, h = blockIdx.y;
    const int tid = threadIdx.x;
    const int lane = tid & 31, warp = tid >> 5;
    const int g = lane >> 2, tig = lane & 3;
    const int m_off = warp * 32;
    const size_t rowbase = (size_t)i * NRES;
    const int hw = h * 16;

    // --- stage Q through Kh, grab fragments ---
    #pragma unroll
    for (int p = 0; p < 4; p++) {
        int idx = tid + p * 384;
        int row = idx >> 2, c = (idx & 3) * 4;
        *reinterpret_cast<uint4*>(Kh + row * KV_STRIDE + c) =
            *reinterpret_cast<const uint4*>(g_qw + (rowbase + row) * 64 + hw + c);
    }
    __syncthreads();
    uint32_t qf[2][2][4];
    #pragma unroll
    for (int mt = 0; mt < 2; mt++) {
        int r = m_off + mt * 16 + g;
        #pragma unroll
        for (int kd = 0; kd < 2; kd++) {
            qf[mt][kd][0] = Kh[ r      * KV_STRIDE + kd * 8 + tig];
            qf[mt][kd][1] = Kh[(r + 8) * KV_STRIDE + kd * 8 + tig];
            qf[mt][kd][2] = Kh[ r      * KV_STRIDE + kd * 8 + tig + 4];
            qf[mt][kd][3] = Kh[(r + 8) * KV_STRIDE + kd * 8 + tig + 4];
        }
    }
    __syncthreads();

    // --- load K, V, mask ---
    #pragma unroll
    for (int p = 0; p < 4; p++) {
        int idx = tid + p * 384;
        int row = idx >> 2, c = (idx & 3) * 4;
        *reinterpret_cast<uint4*>(Kh + row * KV_STRIDE + c) =
            *reinterpret_cast<const uint4*>(g_kw + (rowbase + row) * 64 + hw + c);
        *reinterpret_cast<uint4*>(Vh + row * KV_STRIDE + c) =
            *reinterpret_cast<const uint4*>(g_vw + (rowbase + row) * 64 + hw + c);
    }
    mb[tid] = 1.4426950409e9f * (mask[rowbase + tid] - 1.f);
    __syncthreads();

    float oacc[2][4][4];
    #pragma unroll
    for (int mt = 0; mt < 2; mt++)
        #pragma unroll
        for (int nt = 0; nt < 4; nt++)
            #pragma unroll
            for (int e = 0; e < 4; e++) oacc[mt][nt][e] = 0.f;
    float lsum[2][2] = {{0.f, 0.f}, {0.f, 0.f}};

    const __half* tribh = g_trih + (size_t)h * RTOT;
    const uint32_t vbase = (uint32_t)__cvta_generic_to_shared(Vh) + (lane & 15) * (KV_STRIDE * 4);

    for (int kb = 0; kb < NRES; kb += 32) {
        uint32_t trw[2][2][4];
        float2   mbp[4];
        #pragma unroll
        for (int nt = 0; nt < 4; nt++) {
            int k0 = kb + nt * 8 + 2 * tig;
            mbp[nt] = *reinterpret_cast<float2*>(&mb[k0]);
            #pragma unroll
            for (int mt = 0; mt < 2; mt++) {
                int r = m_off + mt * 16 + g;
                trw[mt][0][nt] = *reinterpret_cast<const uint32_t*>(&tribh[(size_t)r * NRES + k0]);
                trw[mt][1][nt] = *reinterpret_cast<const uint32_t*>(&tribh[(size_t)(r + 8) * NRES + k0]);
            }
        }

        uint32_t pk[2][4][2];
        #pragma unroll
        for (int mt = 0; mt < 2; mt++) {
            float s[4][4];
            #pragma unroll
            for (int nt = 0; nt < 4; nt++)
                #pragma unroll
                for (int e = 0; e < 4; e++) s[nt][e] = 0.f;
            #pragma unroll
            for (int kd = 0; kd < 2; kd++)
                #pragma unroll
                for (int nt = 0; nt < 4; nt++) {
                    int krow = kb + nt * 8 + g;
                    uint32_t b[2] = {Kh[krow * KV_STRIDE + kd * 8 + tig],
                                     Kh[krow * KV_STRIDE + kd * 8 + tig + 4]};
                    mma_f16(s[nt], qf[mt][kd], b);
                }
            #pragma unroll
            for (int nt = 0; nt < 4; nt++) {
                float2 b0 = __half22float2(*reinterpret_cast<__half2*>(&trw[mt][0][nt]));
                float2 b1 = __half22float2(*reinterpret_cast<__half2*>(&trw[mt][1][nt]));
                float p00 = ex2(s[nt][0] + b0.x + mbp[nt].x);
                float p01 = ex2(s[nt][1] + b0.y + mbp[nt].y);
                float p10 = ex2(s[nt][2] + b1.x + mbp[nt].x);
                float p11 = ex2(s[nt][3] + b1.y + mbp[nt].y);
                lsum[mt][0] += p00 + p01;
                lsum[mt][1] += p10 + p11;
                pk[mt][nt][0] = pack_h2(p00, p01);
                pk[mt][nt][1] = pack_h2(p10, p11);
            }
        }

        #pragma unroll
        for (int kg = 0; kg < 2; kg++) {
            #pragma unroll
            for (int nt = 0; nt < 4; nt++) {
                uint32_t b0, b1;
                ldsm_x2_t(b0, b1, vbase + (kb + kg * 16) * (KV_STRIDE * 4) + nt * 16);
                uint32_t bq[2] = {b0, b1};
                uint32_t a0[4] = {pk[0][2*kg][0], pk[0][2*kg][1], pk[0][2*kg+1][0], pk[0][2*kg+1][1]};
                mma_f16(oacc[0][nt], a0, bq);
                uint32_t a1[4] = {pk[1][2*kg][0], pk[1][2*kg][1], pk[1][2*kg+1][0], pk[1][2*kg+1][1]};
                mma_f16(oacc[1][nt], a1, bq);
            }
        }
    }

    // epilogue
    #pragma unroll
    for (int mt = 0; mt < 2; mt++) {
        float la = lsum[mt][0], lb = lsum[mt][1];
        la += __shfl_xor_sync(0xffffffffu, la, 1);
        la += __shfl_xor_sync(0xffffffffu, la, 2);
        lb += __shfl_xor_sync(0xffffffffu, lb, 1);
        lb += __shfl_xor_sync(0xffffffffu, lb, 2);
        float ia = 1.f / la, ib = 1.f / lb;
        size_t rowa = rowbase + m_off + mt * 16 + g;
        size_t rowb = rowa + 8;
        #pragma unroll
        for (int nt = 0; nt < 4; nt++) {
            uint32_t gaw = g_gw[rowa * 64 + hw + nt * 4 + tig];
            uint32_t gbw = g_gw[rowb * 64 + hw + nt * 4 + tig];
            float2 ga = __half22float2(*reinterpret_cast<__half2*>(&gaw));
            float2 gb = __half22float2(*reinterpret_cast<__half2*>(&gbw));
            g_ow[rowa * 64 + hw + nt * 4 + tig] =
                pack_h2(oacc[mt][nt][0] * ia * ga.x, oacc[mt][nt][1] * ia * ga.y);
            g_ow[rowb * 64 + hw + nt * 4 + tig] =
                pack_h2(oacc[mt][nt][2] * ib * gb.x, oacc[mt][nt][3] * ib * gb.y);
        }
    }
}

// ---------------------------------------------------------------------------
// 3. Output GEMM (fp16 mma): g_ow @ w_o + b_o -> out. cp.async staging.
// ---------------------------------------------------------------------------
#define OAS_STRIDE 68
#define OBS_STRIDE 136
#define OUT_SMEM ((128*OAS_STRIDE + 64*OBS_STRIDE) * 4)

__global__ __launch_bounds__(256, 2) void out_kernel(const float* __restrict__ bo,
                                                     float* __restrict__ out) {
    extern __shared__ uint32_t osm[];
    uint32_t* As = osm;                    // [128][68]
    uint32_t* Bs = osm + 128 * OAS_STRIDE; // [64][136]

    const int r0 = blockIdx.x * 128;
    const int tid  = threadIdx.x;
    const int lane = tid & 31, warp = tid >> 5;
    const int g    = lane >> 2, tig = lane & 3;
    const int m_off = (warp >> 1) * 32;
    const int n_off = (warp & 1) * 64;

    const uint32_t asa = (uint32_t)__cvta_generic_to_shared(As);
    const uint32_t bsa = (uint32_t)__cvta_generic_to_shared(Bs);

    // Stage A (g_ow rows): 128 rows x 64 words = 2048 16B chunks, 8/thread
    #pragma unroll
    for (int p = 0; p < 8; p++) {
        int c = tid + p * 256;
        int row = c >> 4, c4 = (c & 15) * 4;
        cp_async16(asa + (row * OAS_STRIDE + c4) * 4,
                   g_ow + (size_t)(r0 + row) * 64 + c4);
    }
    // Stage B (wo pre-converted): 64 rows x 128 words = 2048 chunks, 8/thread
    #pragma unroll
    for (int p = 0; p < 8; p++) {
        int c = tid + p * 256;
        int kp = c >> 5, n4 = (c & 31) * 4;
        cp_async16(bsa + (kp * OBS_STRIDE + n4) * 4,
                   g_w16 + 4 * 8192 + kp * 128 + n4);
    }
    CP_COMMIT();
    CP_WAIT0();
    __syncthreads();

    float acc[2][8][4];
    #pragma unroll
    for (int mt = 0; mt < 2; mt++)
        #pragma unroll
        for (int nt = 0; nt < 8; nt++)
            #pragma unroll
            for (int e = 0; e < 4; e++) acc[mt][nt][e] = 0.f;

    #pragma unroll
    for (int ks = 0; ks < 8; ks++) {
        int kp8 = ks * 8;
        uint32_t af[2][4];
        #pragma unroll
        for (int mt = 0; mt < 2; mt++) {
            int row0 = m_off + mt * 16 + g;
            af[mt][0] = As[ row0      * OAS_STRIDE + kp8 + tig];
            af[mt][1] = As[(row0 + 8) * OAS_STRIDE + kp8 + tig];
            af[mt][2] = As[ row0      * OAS_STRIDE + kp8 + tig + 4];
            af[mt][3] = As[(row0 + 8) * OAS_STRIDE + kp8 + tig + 4];
        }
        uint32_t bf[8][2];
        #pragma unroll
        for (int nt = 0; nt < 8; nt++) {
            int col = n_off + nt * 8 + g;
            bf[nt][0] = Bs[(kp8 + tig    ) * OBS_STRIDE + col];
            bf[nt][1] = Bs[(kp8 + tig + 4) * OBS_STRIDE + col];
        }
        #pragma unroll
        for (int mt = 0; mt < 2; mt++)
            #pragma unroll
            for (int nt = 0; nt < 8; nt++)
                mma_f16(acc[mt][nt], af[mt], bf[nt]);
    }

    #pragma unroll
    for (int mt = 0; mt < 2; mt++) {
        #pragma unroll
        for (int nt = 0; nt < 8; nt++) {
            int row = r0 + m_off + mt * 16 + g;
            int col = n_off + nt * 8 + tig * 2;
            float b0 = bo[col], b1 = bo[col + 1];
            *reinterpret_cast<float2*>(out + (size_t)row * CZ + col) =
                make_float2(acc[mt][nt][0] + b0, acc[mt][nt][1] + b1);
            *reinterpret_cast<float2*>(out + (size_t)(row + 8) * CZ + col) =
                make_float2(acc[mt][nt][2] + b0, acc[mt][nt][3] + b1);
        }
    }
}

// ---------------------------------------------------------------------------
extern "C" void kernel_launch(void* const* d_in, const int* in_sizes, int n_in,
                              void* d_out, int out_size) {
    const float* z      = (const float*)d_in[0];
    const float* mask   = (const float*)d_in[1];
    const float* gamma  = (const float*)d_in[2];
    const float* beta   = (const float*)d_in[3];
    const float* w_bias = (const float*)d_in[4];
    const float* w_q    = (const float*)d_in[5];
    const float* w_k    = (const float*)d_in[6];
    const float* w_v    = (const float*)d_in[7];
    const float* w_g    = (const float*)d_in[8];
    const float* b_g    = (const float*)d_in[9];
    const float* w_o    = (const float*)d_in[10];
    const float* b_o    = (const float*)d_in[11];
    float* out = (float*)d_out;

    (void)cudaFuncSetAttribute(proj_kernel, cudaFuncAttributeMaxDynamicSharedMemorySize, PROJ_SMEM);
    (void)cudaFuncSetAttribute(attn_kernel, cudaFuncAttributeMaxDynamicSharedMemorySize, SMEM_ATTN);
    (void)cudaFuncSetAttribute(out_kernel,  cudaFuncAttributeMaxDynamicSharedMemorySize, OUT_SMEM);

    prep_kernel<<<160, 256>>>(w_q, w_k, w_v, w_g, w_o);
    proj_kernel<<<RTOT / 128, 256, PROJ_SMEM>>>(z, gamma, beta, w_bias, b_g);
    attn_kernel<<<dim3(NRES, NH), 384, SMEM_ATTN>>>(mask);
    out_kernel<<<RTOT / 128, 256, OUT_SMEM>>>(b_o, out);
}

// round 15
// speedup vs baseline: 1.0966x; 1.0199x over previous
#include <cuda_runtime.h>
#include <cuda_fp16.h>
#include <cstdint>

// Problem constants
#define NRES 384
#define CZ   128
#define NH   4
#define CH   32
#define HC   128              // NH*CH
#define RTOT (NRES*NRES)      // 147456
#define LN_EPS 1e-5f
#define Q_SCALE 0.17677669529663687f       // 1/sqrt(32)
#define LOG2E   1.4426950408889634f
#define QS_L2E  (Q_SCALE * LOG2E)

// Scratch (device globals). q/k/v/o/gate stored as packed fp16 pairs:
// 64 words = 128 halves per row; head h occupies words h*16..h*16+15.
__device__ uint32_t g_qw[RTOT * 64];
__device__ uint32_t g_kw[RTOT * 64];
__device__ uint32_t g_vw[RTOT * 64];
__device__ uint32_t g_ow[RTOT * 64];    // gated attention output, fp16 pairs
__device__ uint32_t g_gw[RTOT * 64];    // sigmoid gate, fp16 pairs
__device__ __half   g_trih[NH * RTOT];  // tri bias * log2e, fp16, [h][q*NRES+k]
// Pre-converted weights, packed fp16 k-pairs: [w][kp*128 + n], w: 0q 1k 2v 3g 4o
__device__ uint32_t g_w16[5 * 64 * 128];

// ---------------------------------------------------------------------------
// helpers
// ---------------------------------------------------------------------------
__device__ __forceinline__ void mma_f16(float c[4], const uint32_t a[4], const uint32_t b[2]) {
    asm volatile("mma.sync.aligned.m16n8k16.row.col.f32.f16.f16.f32 "
                 "{%0,%1,%2,%3}, {%4,%5,%6,%7}, {%8,%9}, {%0,%1,%2,%3};"
                 : "+f"(c[0]), "+f"(c[1]), "+f"(c[2]), "+f"(c[3])
                 : "r"(a[0]), "r"(a[1]), "r"(a[2]), "r"(a[3]),
                   "r"(b[0]), "r"(b[1]));
}
__device__ __forceinline__ uint32_t pack_h2(float a, float b) {
    __half2 h = __floats2half2_rn(a, b);
    return *reinterpret_cast<uint32_t*>(&h);
}
__device__ __forceinline__ float ex2(float x) {
    float r; asm("ex2.approx.f32 %0, %1;" : "=f"(r) : "f"(x)); return r;
}
__device__ __forceinline__ void ldsm_x2_t(uint32_t& r0, uint32_t& r1, uint32_t addr) {
    asm volatile("ldmatrix.sync.aligned.m8n8.x2.trans.shared.b16 {%0,%1}, [%2];"
                 : "=r"(r0), "=r"(r1) : "r"(addr));
}
__device__ __forceinline__ void cp_async16(uint32_t saddr, const void* gptr) {
    asm volatile("cp.async.ca.shared.global [%0], [%1], 16;" :: "r"(saddr), "l"(gptr));
}
#define CP_COMMIT() asm volatile("cp.async.commit_group;" ::: "memory")
#define CP_WAIT0()  asm volatile("cp.async.wait_group 0;" ::: "memory")

// ---------------------------------------------------------------------------
// 0. Weight prep: fp32 [128][128] -> packed fp16 k-pair words [64][128]
// ---------------------------------------------------------------------------
__global__ __launch_bounds__(256) void prep_kernel(const float* __restrict__ wq,
                                                   const float* __restrict__ wk,
                                                   const float* __restrict__ wv,
                                                   const float* __restrict__ wg,
                                                   const float* __restrict__ wo) {
    int idx = blockIdx.x * 256 + threadIdx.x;      // 0 .. 40959
    int w = idx >> 13;                              // /8192
    int r = idx & 8191;
    int kp = r >> 7, n = r & 127;
    const float* W = (w == 0) ? wq : (w == 1) ? wk : (w == 2) ? wv : (w == 3) ? wg : wo;
    g_w16[idx] = pack_h2(W[(2 * kp) * 128 + n], W[(2 * kp + 1) * 128 + n]);
}

// ---------------------------------------------------------------------------
// 1. Projection GEMM (fp16 mma), fused LayerNorm, tri via mma.
//    Single-buffer weight staging from pre-converted g_w16 via cp.async.
// ---------------------------------------------------------------------------
#define AS2_STRIDE 68
#define BS2_STRIDE 136
#define PROJ_SMEM ((128*AS2_STRIDE + 64*BS2_STRIDE) * 4)

__global__ __launch_bounds__(256, 2) void proj_kernel(const float* __restrict__ z,
                                                      const float* __restrict__ gamma,
                                                      const float* __restrict__ beta,
                                                      const float* __restrict__ wb,
                                                      const float* __restrict__ bg) {
    extern __shared__ uint32_t psm[];
    uint32_t* As = psm;                    // [128][68] fp16 pairs (zn)
    uint32_t* Bs = psm + 128 * AS2_STRIDE; // [64][136] fp16 k-pairs

    const int r0   = blockIdx.x * 128;
    const int tid  = threadIdx.x;
    const int lane = tid & 31, warp = tid >> 5;
    const int g    = lane >> 2, tig = lane & 3;
    const int m_off = (warp >> 1) * 32;
    const int n_off = (warp & 1) * 64;

    const uint32_t bsa = (uint32_t)__cvta_generic_to_shared(Bs);

    // --- A staging with fused LN (warp w handles row p*8+w) ---
    float4 gm = reinterpret_cast<const float4*>(gamma)[lane];
    float4 bt = reinterpret_cast<const float4*>(beta)[lane];
    #pragma unroll
    for (int p = 0; p < 16; p++) {
        int row = p * 8 + warp;            // local row 0..127
        float4 x = *reinterpret_cast<const float4*>(
            z + (size_t)(r0 + row) * CZ + lane * 4);
        float s  = x.x + x.y + x.z + x.w;
        float ss = x.x*x.x + x.y*x.y + x.z*x.z + x.w*x.w;
        #pragma unroll
        for (int o = 16; o; o >>= 1) {
            s  += __shfl_xor_sync(0xffffffffu, s,  o);
            ss += __shfl_xor_sync(0xffffffffu, ss, o);
        }
        float mean = s * (1.0f / CZ);
        float var  = ss * (1.0f / CZ) - mean * mean;
        float rstd = rsqrtf(var + LN_EPS);
        float n0 = (x.x - mean) * rstd * gm.x + bt.x;
        float n1 = (x.y - mean) * rstd * gm.y + bt.y;
        float n2 = (x.z - mean) * rstd * gm.z + bt.z;
        float n3 = (x.w - mean) * rstd * gm.w + bt.w;
        uint32_t* d = &As[row * AS2_STRIDE + lane * 2];
        d[0] = pack_h2(n0, n1);
        d[1] = pack_h2(n2, n3);
    }
    __syncthreads();   // As visible

    // --- tri bias via mma: As @ wb (padded to 8 cols), scaled by log2e ---
    for (int idx = tid; idx < 64 * 8; idx += 256) {
        int kp = idx >> 3, n = idx & 7;
        float a = (n < NH) ? wb[(2 * kp    ) * NH + n] : 0.f;
        float b = (n < NH) ? wb[(2 * kp + 1) * NH + n] : 0.f;
        Bs[kp * BS2_STRIDE + n] = pack_h2(a, b);
    }
    __syncthreads();
    {
        float tacc[2][4] = {{0.f,0.f,0.f,0.f},{0.f,0.f,0.f,0.f}};
        #pragma unroll
        for (int ks = 0; ks < 8; ks++) {
            int kp8 = ks * 8;
            uint32_t bf[2];
            bf[0] = Bs[(kp8 + tig    ) * BS2_STRIDE + g];
            bf[1] = Bs[(kp8 + tig + 4) * BS2_STRIDE + g];
            #pragma unroll
            for (int mt = 0; mt < 2; mt++) {
                int row0 = m_off + mt * 16 + g;
                uint32_t af[4];
                af[0] = As[ row0      * AS2_STRIDE + kp8 + tig];
                af[1] = As[(row0 + 8) * AS2_STRIDE + kp8 + tig];
                af[2] = As[ row0      * AS2_STRIDE + kp8 + tig + 4];
                af[3] = As[(row0 + 8) * AS2_STRIDE + kp8 + tig + 4];
                mma_f16(tacc[mt], af, bf);
            }
        }
        if ((warp & 1) == 0 && tig < 2) {
            int h0 = 2 * tig, h1 = 2 * tig + 1;
            #pragma unroll
            for (int mt = 0; mt < 2; mt++) {
                int rg = r0 + m_off + mt * 16 + g;
                g_trih[(size_t)h0 * RTOT + rg    ] = __float2half(tacc[mt][0] * LOG2E);
                g_trih[(size_t)h1 * RTOT + rg    ] = __float2half(tacc[mt][1] * LOG2E);
                g_trih[(size_t)h0 * RTOT + rg + 8] = __float2half(tacc[mt][2] * LOG2E);
                g_trih[(size_t)h1 * RTOT + rg + 8] = __float2half(tacc[mt][3] * LOG2E);
            }
        }
    }

    for (int slab = 0; slab < 4; slab++) {
        __syncthreads();   // prior Bs reads done (tri for slab 0)
        // Stage slab weights: 64 rows x 128 words = 2048 16B chunks, 8/thread
        const uint32_t* src = g_w16 + slab * 8192;
        #pragma unroll
        for (int p = 0; p < 8; p++) {
            int c = tid + p * 256;
            int kp = c >> 5, n4 = (c & 31) * 4;
            cp_async16(bsa + (kp * BS2_STRIDE + n4) * 4, src + kp * 128 + n4);
        }
        CP_COMMIT();
        CP_WAIT0();
        __syncthreads();

        float acc[2][8][4];
        #pragma unroll
        for (int mt = 0; mt < 2; mt++)
            #pragma unroll
            for (int nt = 0; nt < 8; nt++)
                #pragma unroll
                for (int e = 0; e < 4; e++) acc[mt][nt][e] = 0.f;

        #pragma unroll
        for (int ks = 0; ks < 8; ks++) {
            int kp8 = ks * 8;
            uint32_t af[2][4];
            #pragma unroll
            for (int mt = 0; mt < 2; mt++) {
                int row0 = m_off + mt * 16 + g;
                af[mt][0] = As[ row0      * AS2_STRIDE + kp8 + tig];
                af[mt][1] = As[(row0 + 8) * AS2_STRIDE + kp8 + tig];
                af[mt][2] = As[ row0      * AS2_STRIDE + kp8 + tig + 4];
                af[mt][3] = As[(row0 + 8) * AS2_STRIDE + kp8 + tig + 4];
            }
            uint32_t bf[8][2];
            #pragma unroll
            for (int nt = 0; nt < 8; nt++) {
                int col = n_off + nt * 8 + g;
                bf[nt][0] = Bs[(kp8 + tig    ) * BS2_STRIDE + col];
                bf[nt][1] = Bs[(kp8 + tig + 4) * BS2_STRIDE + col];
            }
            #pragma unroll
            for (int mt = 0; mt < 2; mt++)
                #pragma unroll
                for (int nt = 0; nt < 8; nt++)
                    mma_f16(acc[mt][nt], af[mt], bf[nt]);
        }

        #pragma unroll
        for (int mt = 0; mt < 2; mt++) {
            int rowa = r0 + m_off + mt * 16 + g;
            #pragma unroll
            for (int nt = 0; nt < 8; nt++) {
                int col = n_off + nt * 8 + tig * 2;      // even
                float c0 = acc[mt][nt][0], c1 = acc[mt][nt][1];
                float c2 = acc[mt][nt][2], c3 = acc[mt][nt][3];
                size_t w0 = (size_t)rowa * 64 + (col >> 1);
                size_t w1 = (size_t)(rowa + 8) * 64 + (col >> 1);
                if (slab == 0) {
                    g_qw[w0] = pack_h2(c0 * QS_L2E, c1 * QS_L2E);
                    g_qw[w1] = pack_h2(c2 * QS_L2E, c3 * QS_L2E);
                } else if (slab == 1) {
                    g_kw[w0] = pack_h2(c0, c1);
                    g_kw[w1] = pack_h2(c2, c3);
                } else if (slab == 2) {
                    g_vw[w0] = pack_h2(c0, c1);
                    g_vw[w1] = pack_h2(c2, c3);
                } else {
                    float b0 = bg[col], b1 = bg[col + 1];
                    g_gw[w0] = pack_h2(1.f / (1.f + __expf(-(c0 + b0))),
                                       1.f / (1.f + __expf(-(c1 + b1))));
                    g_gw[w1] = pack_h2(1.f / (1.f + __expf(-(c2 + b0))),
                                       1.f / (1.f + __expf(-(c3 + b1))));
                }
            }
        }
    }
}

// ---------------------------------------------------------------------------
// 2. Attention (fp16 mma, fp32 accum): one block per (i,h), 384 thr / 12 warps,
//    32 queries per warp. Q fragments loaded direct from global; K/V staged
//    via cp.async (overlapped). exp2-domain softmax.
// ---------------------------------------------------------------------------
#define KV_STRIDE 20
#define SMEM_ATTN ((NRES*KV_STRIDE*2 + NRES) * 4)

__global__ __launch_bounds__(384, 1) void attn_kernel(const float* __restrict__ mask) {
    extern __shared__ uint32_t smu[];
    uint32_t* Kh = smu;                        // [384][20] fp16 pairs
    uint32_t* Vh = smu + NRES * KV_STRIDE;     // [384][20] fp16 pairs
    float*    mb = (float*)(smu + 2 * NRES * KV_STRIDE);  // [384]

    const int i = blockIdx.x, h = blockIdx.y;
    const int tid = threadIdx.x;
    const int lane = tid & 31, warp = tid >> 5;
    const int g = lane >> 2, tig = lane & 3;
    const int m_off = warp * 32;
    const size_t rowbase = (size_t)i * NRES;
    const int hw = h * 16;

    const uint32_t kha = (uint32_t)__cvta_generic_to_shared(Kh);
    const uint32_t vha = (uint32_t)__cvta_generic_to_shared(Vh);

    // --- K/V via cp.async: each 1536 chunks, 4 per thread ---
    #pragma unroll
    for (int p = 0; p < 4; p++) {
        int idx = tid + p * 384;
        int row = idx >> 2, c = (idx & 3) * 4;
        cp_async16(kha + (row * KV_STRIDE + c) * 4, g_kw + (rowbase + row) * 64 + hw + c);
        cp_async16(vha + (row * KV_STRIDE + c) * 4, g_vw + (rowbase + row) * 64 + hw + c);
    }
    CP_COMMIT();
    mb[tid] = 1.4426950409e9f * (mask[rowbase + tid] - 1.f);

    // --- Q fragments straight from global (overlaps cp.async) ---
    uint32_t qf[2][2][4];
    #pragma unroll
    for (int mt = 0; mt < 2; mt++) {
        size_t ra = (rowbase + m_off + mt * 16 + g) * 64 + hw;
        size_t rb = ra + 8 * 64;
        #pragma unroll
        for (int kd = 0; kd < 2; kd++) {
            qf[mt][kd][0] = g_qw[ra + kd * 8 + tig];
            qf[mt][kd][1] = g_qw[rb + kd * 8 + tig];
            qf[mt][kd][2] = g_qw[ra + kd * 8 + tig + 4];
            qf[mt][kd][3] = g_qw[rb + kd * 8 + tig + 4];
        }
    }
    CP_WAIT0();
    __syncthreads();

    float oacc[2][4][4];
    #pragma unroll
    for (int mt = 0; mt < 2; mt++)
        #pragma unroll
        for (int nt = 0; nt < 4; nt++)
            #pragma unroll
            for (int e = 0; e < 4; e++) oacc[mt][nt][e] = 0.f;
    float lsum[2][2] = {{0.f, 0.f}, {0.f, 0.f}};

    const __half* tribh = g_trih + (size_t)h * RTOT;
    const uint32_t vbase = vha + (lane & 15) * (KV_STRIDE * 4);

    for (int kb = 0; kb < NRES; kb += 32) {
        uint32_t trw[2][2][4];
        float2   mbp[4];
        #pragma unroll
        for (int nt = 0; nt < 4; nt++) {
            int k0 = kb + nt * 8 + 2 * tig;
            mbp[nt] = *reinterpret_cast<float2*>(&mb[k0]);
            #pragma unroll
            for (int mt = 0; mt < 2; mt++) {
                int r = m_off + mt * 16 + g;
                trw[mt][0][nt] = *reinterpret_cast<const uint32_t*>(&tribh[(size_t)r * NRES + k0]);
                trw[mt][1][nt] = *reinterpret_cast<const uint32_t*>(&tribh[(size_t)(r + 8) * NRES + k0]);
            }
        }

        uint32_t pk[2][4][2];
        #pragma unroll
        for (int mt = 0; mt < 2; mt++) {
            float s[4][4];
            #pragma unroll
            for (int nt = 0; nt < 4; nt++)
                #pragma unroll
                for (int e = 0; e < 4; e++) s[nt][e] = 0.f;
            #pragma unroll
            for (int kd = 0; kd < 2; kd++)
                #pragma unroll
                for (int nt = 0; nt < 4; nt++) {
                    int krow = kb + nt * 8 + g;
                    uint32_t b[2] = {Kh[krow * KV_STRIDE + kd * 8 + tig],
                                     Kh[krow * KV_STRIDE + kd * 8 + tig + 4]};
                    mma_f16(s[nt], qf[mt][kd], b);
                }
            #pragma unroll
            for (int nt = 0; nt < 4; nt++) {
                float2 b0 = __half22float2(*reinterpret_cast<__half2*>(&trw[mt][0][nt]));
                float2 b1 = __half22float2(*reinterpret_cast<__half2*>(&trw[mt][1][nt]));
                float p00 = ex2(s[nt][0] + b0.x + mbp[nt].x);
                float p01 = ex2(s[nt][1] + b0.y + mbp[nt].y);
                float p10 = ex2(s[nt][2] + b1.x + mbp[nt].x);
                float p11 = ex2(s[nt][3] + b1.y + mbp[nt].y);
                lsum[mt][0] += p00 + p01;
                lsum[mt][1] += p10 + p11;
                pk[mt][nt][0] = pack_h2(p00, p01);
                pk[mt][nt][1] = pack_h2(p10, p11);
            }
        }

        #pragma unroll
        for (int kg = 0; kg < 2; kg++) {
            #pragma unroll
            for (int nt = 0; nt < 4; nt++) {
                uint32_t b0, b1;
                ldsm_x2_t(b0, b1, vbase + (kb + kg * 16) * (KV_STRIDE * 4) + nt * 16);
                uint32_t bq[2] = {b0, b1};
                uint32_t a0[4] = {pk[0][2*kg][0], pk[0][2*kg][1], pk[0][2*kg+1][0], pk[0][2*kg+1][1]};
                mma_f16(oacc[0][nt], a0, bq);
                uint32_t a1[4] = {pk[1][2*kg][0], pk[1][2*kg][1], pk[1][2*kg+1][0], pk[1][2*kg+1][1]};
                mma_f16(oacc[1][nt], a1, bq);
            }
        }
    }

    // epilogue
    #pragma unroll
    for (int mt = 0; mt < 2; mt++) {
        float la = lsum[mt][0], lb = lsum[mt][1];
        la += __shfl_xor_sync(0xffffffffu, la, 1);
        la += __shfl_xor_sync(0xffffffffu, la, 2);
        lb += __shfl_xor_sync(0xffffffffu, lb, 1);
        lb += __shfl_xor_sync(0xffffffffu, lb, 2);
        float ia = 1.f / la, ib = 1.f / lb;
        size_t rowa = rowbase + m_off + mt * 16 + g;
        size_t rowb = rowa + 8;
        #pragma unroll
        for (int nt = 0; nt < 4; nt++) {
            uint32_t gaw = g_gw[rowa * 64 + hw + nt * 4 + tig];
            uint32_t gbw = g_gw[rowb * 64 + hw + nt * 4 + tig];
            float2 ga = __half22float2(*reinterpret_cast<__half2*>(&gaw));
            float2 gb = __half22float2(*reinterpret_cast<__half2*>(&gbw));
            g_ow[rowa * 64 + hw + nt * 4 + tig] =
                pack_h2(oacc[mt][nt][0] * ia * ga.x, oacc[mt][nt][1] * ia * ga.y);
            g_ow[rowb * 64 + hw + nt * 4 + tig] =
                pack_h2(oacc[mt][nt][2] * ib * gb.x, oacc[mt][nt][3] * ib * gb.y);
        }
    }
}

// ---------------------------------------------------------------------------
// 3. Output GEMM (fp16 mma): g_ow @ w_o + b_o -> out. cp.async staging.
// ---------------------------------------------------------------------------
#define OAS_STRIDE 68
#define OBS_STRIDE 136
#define OUT_SMEM ((128*OAS_STRIDE + 64*OBS_STRIDE) * 4)

__global__ __launch_bounds__(256, 2) void out_kernel(const float* __restrict__ bo,
                                                     float* __restrict__ out) {
    extern __shared__ uint32_t osm[];
    uint32_t* As = osm;                    // [128][68]
    uint32_t* Bs = osm + 128 * OAS_STRIDE; // [64][136]

    const int r0 = blockIdx.x * 128;
    const int tid  = threadIdx.x;
    const int lane = tid & 31, warp = tid >> 5;
    const int g    = lane >> 2, tig = lane & 3;
    const int m_off = (warp >> 1) * 32;
    const int n_off = (warp & 1) * 64;

    const uint32_t asa = (uint32_t)__cvta_generic_to_shared(As);
    const uint32_t bsa = (uint32_t)__cvta_generic_to_shared(Bs);

    // Stage A (g_ow rows): 2048 chunks, 8/thread
    #pragma unroll
    for (int p = 0; p < 8; p++) {
        int c = tid + p * 256;
        int row = c >> 4, c4 = (c & 15) * 4;
        cp_async16(asa + (row * OAS_STRIDE + c4) * 4,
                   g_ow + (size_t)(r0 + row) * 64 + c4);
    }
    // Stage B (wo pre-converted): 2048 chunks, 8/thread
    #pragma unroll
    for (int p = 0; p < 8; p++) {
        int c = tid + p * 256;
        int kp = c >> 5, n4 = (c & 31) * 4;
        cp_async16(bsa + (kp * OBS_STRIDE + n4) * 4,
                   g_w16 + 4 * 8192 + kp * 128 + n4);
    }
    CP_COMMIT();
    CP_WAIT0();
    __syncthreads();

    float acc[2][8][4];
    #pragma unroll
    for (int mt = 0; mt < 2; mt++)
        #pragma unroll
        for (int nt = 0; nt < 8; nt++)
            #pragma unroll
            for (int e = 0; e < 4; e++) acc[mt][nt][e] = 0.f;

    #pragma unroll
    for (int ks = 0; ks < 8; ks++) {
        int kp8 = ks * 8;
        uint32_t af[2][4];
        #pragma unroll
        for (int mt = 0; mt < 2; mt++) {
            int row0 = m_off + mt * 16 + g;
            af[mt][0] = As[ row0      * OAS_STRIDE + kp8 + tig];
            af[mt][1] = As[(row0 + 8) * OAS_STRIDE + kp8 + tig];
            af[mt][2] = As[ row0      * OAS_STRIDE + kp8 + tig + 4];
            af[mt][3] = As[(row0 + 8) * OAS_STRIDE + kp8 + tig + 4];
        }
        uint32_t bf[8][2];
        #pragma unroll
        for (int nt = 0; nt < 8; nt++) {
            int col = n_off + nt * 8 + g;
            bf[nt][0] = Bs[(kp8 + tig    ) * OBS_STRIDE + col];
            bf[nt][1] = Bs[(kp8 + tig + 4) * OBS_STRIDE + col];
        }
        #pragma unroll
        for (int mt = 0; mt < 2; mt++)
            #pragma unroll
            for (int nt = 0; nt < 8; nt++)
                mma_f16(acc[mt][nt], af[mt], bf[nt]);
    }

    #pragma unroll
    for (int mt = 0; mt < 2; mt++) {
        #pragma unroll
        for (int nt = 0; nt < 8; nt++) {
            int row = r0 + m_off + mt * 16 + g;
            int col = n_off + nt * 8 + tig * 2;
            float b0 = bo[col], b1 = bo[col + 1];
            *reinterpret_cast<float2*>(out + (size_t)row * CZ + col) =
                make_float2(acc[mt][nt][0] + b0, acc[mt][nt][1] + b1);
            *reinterpret_cast<float2*>(out + (size_t)(row + 8) * CZ + col) =
                make_float2(acc[mt][nt][2] + b0, acc[mt][nt][3] + b1);
        }
    }
}

// ---------------------------------------------------------------------------
extern "C" void kernel_launch(void* const* d_in, const int* in_sizes, int n_in,
                              void* d_out, int out_size) {
    const float* z      = (const float*)d_in[0];
    const float* mask   = (const float*)d_in[1];
    const float* gamma  = (const float*)d_in[2];
    const float* beta   = (const float*)d_in[3];
    const float* w_bias = (const float*)d_in[4];
    const float* w_q    = (const float*)d_in[5];
    const float* w_k    = (const float*)d_in[6];
    const float* w_v    = (const float*)d_in[7];
    const float* w_g    = (const float*)d_in[8];
    const float* b_g    = (const float*)d_in[9];
    const float* w_o    = (const float*)d_in[10];
    const float* b_o    = (const float*)d_in[11];
    float* out = (float*)d_out;

    (void)cudaFuncSetAttribute(proj_kernel, cudaFuncAttributeMaxDynamicSharedMemorySize, PROJ_SMEM);
    (void)cudaFuncSetAttribute(attn_kernel, cudaFuncAttributeMaxDynamicSharedMemorySize, SMEM_ATTN);
    (void)cudaFuncSetAttribute(out_kernel,  cudaFuncAttributeMaxDynamicSharedMemorySize, OUT_SMEM);

    prep_kernel<<<160, 256>>>(w_q, w_k, w_v, w_g, w_o);
    proj_kernel<<<RTOT / 128, 256, PROJ_SMEM>>>(z, gamma, beta, w_bias, b_g);
    attn_kernel<<<dim3(NRES, NH), 384, SMEM_ATTN>>>(mask);
    out_kernel<<<RTOT / 128, 256, OUT_SMEM>>>(b_o, out);
}